// round 7
// baseline (speedup 1.0000x reference)
#include <cuda_runtime.h>
#include <stdint.h>

// Problem constants (fixed shapes from reference)
#define DET      1024
#define T_TOT    3072                 // DET * 3 replications
#define BATCH    256
#define CLAMP_V  50.0f
#define SOFT_ROW (1025 * 64)          // soft window rows * 64 states

#define WPB      16                   // warps per block (one batch each)

// Survivor decisions: one byte per (batch, step t-1024, lane).
// bit0 = decision of state l (<32), bit1 = decision of state l+32.  16 MB.
__device__ uint8_t g_sur[(size_t)BATCH * 2048 * 32];
// Per-chunk traceback maps: [batch][chunk(64)][entry(64)] -> exit state. 1 MB.
__device__ uint8_t g_map[(size_t)BATCH * 64 * 64];

// Edge code: for new state n with predecessor p, coded bits are
//   c0 = (n&1) ^ p1 ^ p2 ^ p4 ^ p5 ;  c1 = (n&1) ^ p0 ^ p1 ^ p2 ^ p5
// bm = (1-2c0)*llr0 + (1-2c1)*llr1 = sgn * ((c0^c1) ? (llr0-llr1) : (llr0+llr1))
__device__ __forceinline__ void edge_code(int n, int p, float& sgn, int& dif)
{
    int c0 = ((n & 1) ^ (p >> 1) ^ (p >> 2) ^ (p >> 4) ^ (p >> 5)) & 1;
    int c1 = ((n & 1) ^  p       ^ (p >> 1) ^ (p >> 2) ^ (p >> 5)) & 1;
    sgn = c0 ? -1.0f : 1.0f;
    dif = (c0 ^ c1) & 1;
}

__device__ __forceinline__ float clipf(float v)
{
    return fminf(fmaxf(v, -CLAMP_V), CLAMP_V);
}

// Warp sum broadcast, 2 shuffle rounds (radix 8 then radix 4).
// All shuffles within a round are independent; grouping is xor-symmetric +
// commutative -> bit-identical result on every lane (uniform mean).
__device__ __forceinline__ float warp_sum_r84(float s0)
{
    float x1 = __shfl_xor_sync(0xffffffffu, s0, 1);
    float x2 = __shfl_xor_sync(0xffffffffu, s0, 2);
    float x3 = __shfl_xor_sync(0xffffffffu, s0, 3);
    float x4 = __shfl_xor_sync(0xffffffffu, s0, 4);
    float x5 = __shfl_xor_sync(0xffffffffu, s0, 5);
    float x6 = __shfl_xor_sync(0xffffffffu, s0, 6);
    float x7 = __shfl_xor_sync(0xffffffffu, s0, 7);
    float s1 = ((s0 + x1) + (x2 + x3)) + ((x4 + x5) + (x6 + x7));
    float y8  = __shfl_xor_sync(0xffffffffu, s1, 8);
    float y16 = __shfl_xor_sync(0xffffffffu, s1, 16);
    float y24 = __shfl_xor_sync(0xffffffffu, s1, 24);
    return (s1 + y8) + (y16 + y24);
}

// One full ACS step. Carried: va/vb = UNNORMALIZED max-results of the
// previous step, s = their warp sum. Destination applies the zero-lag
// normalization p = clip(fma(-1/64, s, g)) — exact reference semantics.
#define ACS_STEP(IA, IB)                                                     \
    float wS  = wt * (ll.x + ll.y);                                          \
    float wD  = wt * (ll.x - ll.y);                                          \
    float wA0 = dA0 ? wD : wS;                                               \
    float wA1 = dA1 ? wD : wS;                                               \
    float wB0 = dB0 ? wD : wS;                                               \
    float wB1 = dB1 ? wD : wS;                                               \
    float gA0 = __shfl_sync(0xffffffffu, va, h);                             \
    float gA1 = __shfl_sync(0xffffffffu, vb, h);                             \
    float gB0 = __shfl_sync(0xffffffffu, va, h + 16);                        \
    float gB1 = __shfl_sync(0xffffffffu, vb, h + 16);                        \
    float pA0 = clipf(fmaf(-0.015625f, s, gA0));                             \
    float pA1 = clipf(fmaf(-0.015625f, s, gA1));                             \
    float pB0 = clipf(fmaf(-0.015625f, s, gB0));                             \
    float pB1 = clipf(fmaf(-0.015625f, s, gB1));                             \
    float cA0 = fmaf(sA0, wA0, pA0);                                         \
    float cA1 = fmaf(sA1, wA1, pA1);                                         \
    float cB0 = fmaf(sB0, wB0, pB0);                                         \
    float cB1 = fmaf(sB1, wB1, pB1);                                         \
    float nva = fmaxf(cA0, cA1);                                             \
    float nvb = fmaxf(cB0, cB1);                                             \
    bool  IA  = cA1 > cA0;                                                   \
    bool  IB  = cB1 > cB0;                                                   \
    va = nva;  vb = nvb;                                                     \
    s  = warp_sum_r84(nva + nvb);                                            \
    ll = lln;  wt = wn;

// ---------------------------------------------------------------------------
// Forward ACS: WPB independent warps per block, one batch per warp.
// 4 warps per SMSP fill each other's dependency-stall slots (the recurrence
// is chain-bound per warp but the warps are independent across batches).
// Lane l holds states l (va) and l+32 (vb); predecessors of state l live in
// lane l>>1, of state l+32 in lane (l>>1)+16. Arithmetic identical to R6.
// ---------------------------------------------------------------------------
__global__ void __launch_bounds__(32 * WPB, 1)
wcva_fwd(const float* __restrict__ x, const float* __restrict__ w,
         float* __restrict__ soft)
{
    const int b = blockIdx.x * WPB + (threadIdx.x >> 5);
    const int l = threadIdx.x & 31;
    const int h = l >> 1;

    const float2* __restrict__ xrow = (const float2*)(x + (size_t)b * (DET * 2));
    float* __restrict__ softrow = soft + (size_t)b * SOFT_ROW;
    uint8_t* __restrict__ surrow = g_sur + (size_t)b * 2048 * 32 + l;

    float sA0, sA1, sB0, sB1;
    int   dA0, dA1, dB0, dB1;
    edge_code(l,      h,      sA0, dA0);
    edge_code(l,      h + 32, sA1, dA1);
    edge_code(l + 32, h + 16, sB0, dB0);
    edge_code(l + 32, h + 48, sB1, dB1);

    // Carried state: unnormalized v, its warp sum s.
    // s = 0 makes step 0 consume in_prob0 raw, exactly like the reference.
    float va = (l == 0) ? CLAMP_V : 0.0f;   // state l
    float vb = 0.0f;                        // state l+32
    float s  = 0.0f;

    float2 ll = xrow[0];
    float  wt = w[0];

    // ---- segment 1: t in [0, 1024)  (no outputs) ----
#pragma unroll 2
    for (int t = 0; t < 1024; t++) {
        float2 lln = xrow[(t + 1) & (DET - 1)];
        float  wn  = __ldg(w + t + 1);
        ACS_STEP(ia_, ib_)
        (void)ia_; (void)ib_;
    }

    // ---- segment 2: t in [1024, 2049) ----
    // Every iteration: soft row for step t-1 (in [1023, 2047]) from the OLD
    // carried (va, vb, s), then the ACS step, then the survivor byte for t.
#pragma unroll 2
    for (int t = 1024; t < 2049; t++) {
        float2 lln = xrow[(t + 1) & (DET - 1)];
        float  wn  = __ldg(w + t + 1);

        // soft output of step t-1 (same formula as the decision-path p)
        {
            int r = (t - 1024) * 64;
            softrow[r + l]      = clipf(fmaf(-0.015625f, s, va));
            softrow[r + l + 32] = clipf(fmaf(-0.015625f, s, vb));
        }

        ACS_STEP(ia, ib)

        surrow[(size_t)(t - 1024) * 32] =
            (uint8_t)((ia ? 1 : 0) | (ib ? 2 : 0));
    }

    // ---- segment 3: t in [2049, T_TOT)  (survivor bytes only) ----
#pragma unroll 2
    for (int t = 2049; t < T_TOT; t++) {
        int tn = (t + 1 < T_TOT) ? t + 1 : t;
        float2 lln = xrow[tn & (DET - 1)];
        float  wn  = __ldg(w + tn);
        ACS_STEP(ia, ib)
        surrow[(size_t)(t - 1024) * 32] =
            (uint8_t)((ia ? 1 : 0) | (ib ? 2 : 0));
    }
}

// ---------------------------------------------------------------------------
// Traceback phase A: per (batch, chunk) build the 64-entry state map over
// 32 survivor steps. Chunk c covers s = 2047-32c .. 2016-32c (descending).
// ---------------------------------------------------------------------------
__global__ void __launch_bounds__(64)
tb_maps()
{
    __shared__ uint8_t rows[1024];     // 32 steps x 32 lanes

    const int b = blockIdx.x >> 6;
    const int c = blockIdx.x & 63;
    const int s0 = 2047 - 32 * c;      // top (first-processed) row

    const uint4* __restrict__ src =
        (const uint4*)(g_sur + (((size_t)b * 2048) + (s0 - 31)) * 32);
    ((uint4*)rows)[threadIdx.x] = src[threadIdx.x];   // 64 x 16B = 1 KB
    __syncthreads();

    int st = threadIdx.x;              // entry state
#pragma unroll
    for (int k = 0; k < 32; k++) {
        uint8_t byt = rows[(31 - k) * 32 + (st & 31)];   // row s0-k
        int ind = (byt >> (st >> 5)) & 1;
        st = (st >> 1) + (ind << 5);
    }
    g_map[((size_t)b << 12) + (c << 6) + threadIdx.x] = (uint8_t)st;
}

// ---------------------------------------------------------------------------
// Traceback phase B+C: per batch, compose chunk maps serially from state 0
// at t = T-1, then re-trace the 32 output chunks (s < 1024) and emit bits.
// ---------------------------------------------------------------------------
__global__ void __launch_bounds__(256)
tb_emit(float* __restrict__ dec)
{
    __shared__ uint8_t smap[4096];     // 64 chunks x 64 entries
    __shared__ uint8_t ssur[32768];    // survivor bytes for s in [0, 1024)
    __shared__ uint8_t sentry[64];

    const int b   = blockIdx.x;
    const int tid = threadIdx.x;

    ((uint4*)smap)[tid] = ((const uint4*)(g_map + ((size_t)b << 12)))[tid];

    const uint4* __restrict__ ss = (const uint4*)(g_sur + (size_t)b * 2048 * 32);
#pragma unroll
    for (int i = 0; i < 8; i++)
        ((uint4*)ssur)[tid + 256 * i] = ss[tid + 256 * i];
    __syncthreads();

    if (tid == 0) {
        int st = 0;
        for (int c = 0; c < 64; c++) {
            sentry[c] = (uint8_t)st;
            st = smap[(c << 6) + st];
        }
    }
    __syncthreads();

    if (tid < 32) {
        int c  = 32 + tid;             // output chunks: s0 = 1023-32*tid
        int st = sentry[c];
        float* __restrict__ drow = dec + (size_t)b * DET;
        int s0 = 2047 - 32 * c;
#pragma unroll
        for (int k = 0; k < 32; k++) {
            int s = s0 - k;
            drow[s] = (float)(1 - (st & 1));     // bit from state BEFORE update
            uint8_t byt = ssur[s * 32 + (st & 31)];
            int ind = (byt >> (st >> 5)) & 1;
            st = (st >> 1) + (ind << 5);
        }
    }
}

// ---------------------------------------------------------------------------
// Harness entry. Output layout: decoded_words (256*1024 f32) then soft
// (256*65600 f32), concatenated.
// ---------------------------------------------------------------------------
extern "C" void kernel_launch(void* const* d_in, const int* in_sizes, int n_in,
                              void* d_out, int out_size)
{
    const float* x  = (const float*)d_in[0];   // (256, 2048)
    const float* wv = (const float*)d_in[1];   // (3072,)
    float* out  = (float*)d_out;

    float* dec  = out;                          // 256*1024
    float* soft = out + (size_t)BATCH * DET;    // 256*65600

    wcva_fwd<<<BATCH / WPB, 32 * WPB>>>(x, wv, soft);
    tb_maps<<<BATCH * 64, 64>>>();
    tb_emit<<<BATCH, 256>>>(dec);
}

// round 9
// speedup vs baseline: 2.5603x; 2.5603x over previous
#include <cuda_runtime.h>
#include <stdint.h>

// Problem constants (fixed shapes from reference)
#define DET      1024
#define T_TOT    3072                 // DET * 3 replications
#define BATCH    256
#define CLAMP_V  50.0f
#define SOFT_ROW (1025 * 64)          // soft window rows * 64 states

// Windowed Viterbi, balanced chunks of 1536 steps each:
//   chunk 0: t in [0, 1536)      EXACT (true init, no approximation)
//   chunk k>0: warm-up W=1024 from uniform metric, body of 512 steps.
// Outputs only needed for t >= 1023. Bodies:
//   ck0 [1023,1536)  ck1 [1536,2048)  ck2 [2048,2560)  ck3 [2560,3072)
#define NCH      4
#define W_UP     1024

// Survivor decisions: one byte per (batch, step t-1024, lane).
// bit0 = decision of state l (<32), bit1 = decision of state l+32.  16 MB.
__device__ uint8_t g_sur[(size_t)BATCH * 2048 * 32];
// Per-chunk traceback maps: [batch][chunk(64)][entry(64)] -> exit state. 1 MB.
__device__ uint8_t g_map[(size_t)BATCH * 64 * 64];

// Edge code: for new state n with predecessor p, coded bits are
//   c0 = (n&1) ^ p1 ^ p2 ^ p4 ^ p5 ;  c1 = (n&1) ^ p0 ^ p1 ^ p2 ^ p5
// bm = (1-2c0)*llr0 + (1-2c1)*llr1 = sgn * ((c0^c1) ? (llr0-llr1) : (llr0+llr1))
__device__ __forceinline__ void edge_code(int n, int p, float& sgn, int& dif)
{
    int c0 = ((n & 1) ^ (p >> 1) ^ (p >> 2) ^ (p >> 4) ^ (p >> 5)) & 1;
    int c1 = ((n & 1) ^  p       ^ (p >> 1) ^ (p >> 2) ^ (p >> 5)) & 1;
    sgn = c0 ? -1.0f : 1.0f;
    dif = (c0 ^ c1) & 1;
}

__device__ __forceinline__ float clipf(float v)
{
    return fminf(fmaxf(v, -CLAMP_V), CLAMP_V);
}

// Warp sum broadcast, 2 shuffle rounds (radix 8 then radix 4).
// All shuffles within a round are independent; grouping is xor-symmetric +
// commutative -> bit-identical result on every lane (uniform mean).
__device__ __forceinline__ float warp_sum_r84(float s0)
{
    float x1 = __shfl_xor_sync(0xffffffffu, s0, 1);
    float x2 = __shfl_xor_sync(0xffffffffu, s0, 2);
    float x3 = __shfl_xor_sync(0xffffffffu, s0, 3);
    float x4 = __shfl_xor_sync(0xffffffffu, s0, 4);
    float x5 = __shfl_xor_sync(0xffffffffu, s0, 5);
    float x6 = __shfl_xor_sync(0xffffffffu, s0, 6);
    float x7 = __shfl_xor_sync(0xffffffffu, s0, 7);
    float s1 = ((s0 + x1) + (x2 + x3)) + ((x4 + x5) + (x6 + x7));
    float y8  = __shfl_xor_sync(0xffffffffu, s1, 8);
    float y16 = __shfl_xor_sync(0xffffffffu, s1, 16);
    float y24 = __shfl_xor_sync(0xffffffffu, s1, 24);
    return (s1 + y8) + (y16 + y24);
}

// One full ACS step (identical arithmetic to the R6 passing kernel).
// Carried: va/vb = UNNORMALIZED max-results of the previous step, s = their
// warp sum. Destination applies zero-lag normalization p = clip(fma(-1/64,s,g)).
#define ACS_STEP(IA, IB)                                                     \
    float wS  = wt * (ll.x + ll.y);                                          \
    float wD  = wt * (ll.x - ll.y);                                          \
    float wA0 = dA0 ? wD : wS;                                               \
    float wA1 = dA1 ? wD : wS;                                               \
    float wB0 = dB0 ? wD : wS;                                               \
    float wB1 = dB1 ? wD : wS;                                               \
    float gA0 = __shfl_sync(0xffffffffu, va, h);                             \
    float gA1 = __shfl_sync(0xffffffffu, vb, h);                             \
    float gB0 = __shfl_sync(0xffffffffu, va, h + 16);                        \
    float gB1 = __shfl_sync(0xffffffffu, vb, h + 16);                        \
    float pA0 = clipf(fmaf(-0.015625f, s, gA0));                             \
    float pA1 = clipf(fmaf(-0.015625f, s, gA1));                             \
    float pB0 = clipf(fmaf(-0.015625f, s, gB0));                             \
    float pB1 = clipf(fmaf(-0.015625f, s, gB1));                             \
    float cA0 = fmaf(sA0, wA0, pA0);                                         \
    float cA1 = fmaf(sA1, wA1, pA1);                                         \
    float cB0 = fmaf(sB0, wB0, pB0);                                         \
    float cB1 = fmaf(sB1, wB1, pB1);                                         \
    float nva = fmaxf(cA0, cA1);                                             \
    float nvb = fmaxf(cB0, cB1);                                             \
    bool  IA  = cA1 > cA0;                                                   \
    bool  IB  = cB1 > cB0;                                                   \
    va = nva;  vb = nvb;                                                     \
    s  = warp_sum_r84(nva + nvb);                                            \
    ll = lln;  wt = wn;

// ---------------------------------------------------------------------------
// Forward ACS, windowed: one 32-thread block per (batch, chunk).
// Lane l holds states l (va) and l+32 (vb); predecessors of state l live in
// lane l>>1, of state l+32 in lane (l>>1)+16.
// ---------------------------------------------------------------------------
__global__ void __launch_bounds__(32, 1)
wcva_fwd(const float* __restrict__ x, const float* __restrict__ w,
         float* __restrict__ soft)
{
    const int b  = blockIdx.x >> 2;          // batch
    const int ck = blockIdx.x & 3;           // chunk

    const int body0 = (ck == 0) ? 1023 : 1024 + 512 * ck;
    const int body1 = (ck == 0) ? 1536 : body0 + 512;
    const int t0    = (ck == 0) ? 0 : body0 - W_UP;

    const int l = threadIdx.x;
    const int h = l >> 1;

    const float2* __restrict__ xrow = (const float2*)(x + (size_t)b * (DET * 2));
    float* __restrict__ softrow = soft + (size_t)b * SOFT_ROW;
    uint8_t* __restrict__ surrow = g_sur + (size_t)b * 2048 * 32 + l;

    float sA0, sA1, sB0, sB1;
    int   dA0, dA1, dB0, dB1;
    edge_code(l,      h,      sA0, dA0);
    edge_code(l,      h + 32, sA1, dA1);
    edge_code(l + 32, h + 16, sB0, dB0);
    edge_code(l + 32, h + 48, sB1, dB1);

    // Chunk 0 starts from the TRUE initial condition (exact run).
    // Chunks k>0 cold-start from a uniform metric; the W_UP warm-up steps
    // couple them to the true trajectory (uniform offsets are cancelled by
    // the per-step mean subtraction once survivors merge).
    float va = (ck == 0 && l == 0) ? CLAMP_V : 0.0f;   // state l
    float vb = 0.0f;                                    // state l+32
    float s  = 0.0f;

    float2 ll = xrow[t0 & (DET - 1)];
    float  wt = __ldg(w + t0);

    // ---- warm-up / exact prefix: t in [t0, body0)  (no outputs) ----
#pragma unroll 2
    for (int t = t0; t < body0; t++) {
        float2 lln = xrow[(t + 1) & (DET - 1)];
        float  wn  = __ldg(w + t + 1);
        ACS_STEP(ia_, ib_)
        (void)ia_; (void)ib_;
    }

    // ---- body: t in [body0, body1) ----
    // After the step: survivor byte for t (t >= 1024), soft row for t
    // (t in [1023, 2047]) from the new post-step (va, vb, s).
#pragma unroll 2
    for (int t = body0; t < body1; t++) {
        int tn = (t + 1 < T_TOT) ? t + 1 : t;
        float2 lln = xrow[tn & (DET - 1)];
        float  wn  = __ldg(w + tn);

        ACS_STEP(ia, ib)

        if (t >= 1024)
            surrow[(size_t)(t - 1024) * 32] =
                (uint8_t)((ia ? 1 : 0) | (ib ? 2 : 0));

        if (t < 2048) {                      // t >= 1023 guaranteed by body0
            int r = (t - 1023) * 64;
            softrow[r + l]      = clipf(fmaf(-0.015625f, s, va));
            softrow[r + l + 32] = clipf(fmaf(-0.015625f, s, vb));
        }
    }
}

// ---------------------------------------------------------------------------
// Traceback phase A: per (batch, chunk) build the 64-entry state map over
// 32 survivor steps. Chunk c covers s = 2047-32c .. 2016-32c (descending).
// ---------------------------------------------------------------------------
__global__ void __launch_bounds__(64)
tb_maps()
{
    __shared__ uint8_t rows[1024];     // 32 steps x 32 lanes

    const int b = blockIdx.x >> 6;
    const int c = blockIdx.x & 63;
    const int s0 = 2047 - 32 * c;      // top (first-processed) row

    const uint4* __restrict__ src =
        (const uint4*)(g_sur + (((size_t)b * 2048) + (s0 - 31)) * 32);
    ((uint4*)rows)[threadIdx.x] = src[threadIdx.x];   // 64 x 16B = 1 KB
    __syncthreads();

    int st = threadIdx.x;              // entry state
#pragma unroll
    for (int k = 0; k < 32; k++) {
        uint8_t byt = rows[(31 - k) * 32 + (st & 31)];   // row s0-k
        int ind = (byt >> (st >> 5)) & 1;
        st = (st >> 1) + (ind << 5);
    }
    g_map[((size_t)b << 12) + (c << 6) + threadIdx.x] = (uint8_t)st;
}

// ---------------------------------------------------------------------------
// Traceback phase B+C: per batch, compose chunk maps serially from state 0
// at t = T-1, then re-trace the 32 output chunks (s < 1024) and emit bits.
// ---------------------------------------------------------------------------
__global__ void __launch_bounds__(256)
tb_emit(float* __restrict__ dec)
{
    __shared__ uint8_t smap[4096];     // 64 chunks x 64 entries
    __shared__ uint8_t ssur[32768];    // survivor bytes for s in [0, 1024)
    __shared__ uint8_t sentry[64];

    const int b   = blockIdx.x;
    const int tid = threadIdx.x;

    ((uint4*)smap)[tid] = ((const uint4*)(g_map + ((size_t)b << 12)))[tid];

    const uint4* __restrict__ ss = (const uint4*)(g_sur + (size_t)b * 2048 * 32);
#pragma unroll
    for (int i = 0; i < 8; i++)
        ((uint4*)ssur)[tid + 256 * i] = ss[tid + 256 * i];
    __syncthreads();

    if (tid == 0) {
        int st = 0;
        for (int c = 0; c < 64; c++) {
            sentry[c] = (uint8_t)st;
            st = smap[(c << 6) + st];
        }
    }
    __syncthreads();

    if (tid < 32) {
        int c  = 32 + tid;             // output chunks: s0 = 1023-32*tid
        int st = sentry[c];
        float* __restrict__ drow = dec + (size_t)b * DET;
        int s0 = 2047 - 32 * c;
#pragma unroll
        for (int k = 0; k < 32; k++) {
            int s = s0 - k;
            drow[s] = (float)(1 - (st & 1));     // bit from state BEFORE update
            uint8_t byt = ssur[s * 32 + (st & 31)];
            int ind = (byt >> (st >> 5)) & 1;
            st = (st >> 1) + (ind << 5);
        }
    }
}

// ---------------------------------------------------------------------------
// Harness entry. Output layout: decoded_words (256*1024 f32) then soft
// (256*65600 f32), concatenated.
// ---------------------------------------------------------------------------
extern "C" void kernel_launch(void* const* d_in, const int* in_sizes, int n_in,
                              void* d_out, int out_size)
{
    const float* x  = (const float*)d_in[0];   // (256, 2048)
    const float* wv = (const float*)d_in[1];   // (3072,)
    float* out  = (float*)d_out;

    float* dec  = out;                          // 256*1024
    float* soft = out + (size_t)BATCH * DET;    // 256*65600

    wcva_fwd<<<BATCH * NCH, 32>>>(x, wv, soft);
    tb_maps<<<BATCH * 64, 64>>>();
    tb_emit<<<BATCH, 256>>>(dec);
}

// round 11
// speedup vs baseline: 2.9705x; 1.1602x over previous
#include <cuda_runtime.h>
#include <stdint.h>

// Problem constants (fixed shapes from reference)
#define DET      1024
#define T_TOT    3072                 // DET * 3 replications
#define BATCH    256
#define CLAMP_V  50.0f
#define SOFT_ROW (1025 * 64)          // soft window rows * 64 states

// Windowed Viterbi: 8 chunks per batch, every chunk cold-started from a
// uniform metric W_UP steps before its body (survivor merge makes the body
// match the true run; uniform offsets cancel exactly in mean-subtraction).
//   chunk 0: body [1023, 1280)   chunks k>0: body [1280+256(k-1), +256)
// Bodies cover [1023, 3072) exactly. Chunks 0-3 lie in the soft window
// [1023, 2047]; chunks 4-7 produce survivor bytes only.
#define NCH      8
#define W_UP     704

// Survivor decisions: one byte per (batch, step t-1024, lane).
// bit0 = decision of state l (<32), bit1 = decision of state l+32.  16 MB.
__device__ uint8_t g_sur[(size_t)BATCH * 2048 * 32];
// Per-chunk traceback maps: [batch][chunk(64)][entry(64)] -> exit state. 1 MB.
__device__ uint8_t g_map[(size_t)BATCH * 64 * 64];

// Edge code: for new state n with predecessor p, coded bits are
//   c0 = (n&1) ^ p1 ^ p2 ^ p4 ^ p5 ;  c1 = (n&1) ^ p0 ^ p1 ^ p2 ^ p5
// bm = (1-2c0)*llr0 + (1-2c1)*llr1 = sgn * ((c0^c1) ? (llr0-llr1) : (llr0+llr1))
__device__ __forceinline__ void edge_code(int n, int p, float& sgn, int& dif)
{
    int c0 = ((n & 1) ^ (p >> 1) ^ (p >> 2) ^ (p >> 4) ^ (p >> 5)) & 1;
    int c1 = ((n & 1) ^  p       ^ (p >> 1) ^ (p >> 2) ^ (p >> 5)) & 1;
    sgn = c0 ? -1.0f : 1.0f;
    dif = (c0 ^ c1) & 1;
}

__device__ __forceinline__ float clipf(float v)
{
    return fminf(fmaxf(v, -CLAMP_V), CLAMP_V);
}

// Warp sum broadcast, 2 shuffle rounds (radix 8 then radix 4).
// All shuffles within a round are independent; grouping is xor-symmetric +
// commutative -> bit-identical result on every lane (uniform mean).
__device__ __forceinline__ float warp_sum_r84(float s0)
{
    float x1 = __shfl_xor_sync(0xffffffffu, s0, 1);
    float x2 = __shfl_xor_sync(0xffffffffu, s0, 2);
    float x3 = __shfl_xor_sync(0xffffffffu, s0, 3);
    float x4 = __shfl_xor_sync(0xffffffffu, s0, 4);
    float x5 = __shfl_xor_sync(0xffffffffu, s0, 5);
    float x6 = __shfl_xor_sync(0xffffffffu, s0, 6);
    float x7 = __shfl_xor_sync(0xffffffffu, s0, 7);
    float s1 = ((s0 + x1) + (x2 + x3)) + ((x4 + x5) + (x6 + x7));
    float y8  = __shfl_xor_sync(0xffffffffu, s1, 8);
    float y16 = __shfl_xor_sync(0xffffffffu, s1, 16);
    float y24 = __shfl_xor_sync(0xffffffffu, s1, 24);
    return (s1 + y8) + (y16 + y24);
}

// One full ACS step (identical arithmetic to the R6/R9 passing kernels).
// Carried: va/vb = UNNORMALIZED max-results of the previous step, s = their
// warp sum. Destination applies zero-lag normalization p = clip(fma(-1/64,s,g)).
#define ACS_STEP(IA, IB)                                                     \
    float wS  = wt * (ll.x + ll.y);                                          \
    float wD  = wt * (ll.x - ll.y);                                          \
    float wA0 = dA0 ? wD : wS;                                               \
    float wA1 = dA1 ? wD : wS;                                               \
    float wB0 = dB0 ? wD : wS;                                               \
    float wB1 = dB1 ? wD : wS;                                               \
    float gA0 = __shfl_sync(0xffffffffu, va, h);                             \
    float gA1 = __shfl_sync(0xffffffffu, vb, h);                             \
    float gB0 = __shfl_sync(0xffffffffu, va, h + 16);                        \
    float gB1 = __shfl_sync(0xffffffffu, vb, h + 16);                        \
    float pA0 = clipf(fmaf(-0.015625f, s, gA0));                             \
    float pA1 = clipf(fmaf(-0.015625f, s, gA1));                             \
    float pB0 = clipf(fmaf(-0.015625f, s, gB0));                             \
    float pB1 = clipf(fmaf(-0.015625f, s, gB1));                             \
    float cA0 = fmaf(sA0, wA0, pA0);                                         \
    float cA1 = fmaf(sA1, wA1, pA1);                                         \
    float cB0 = fmaf(sB0, wB0, pB0);                                         \
    float cB1 = fmaf(sB1, wB1, pB1);                                         \
    float nva = fmaxf(cA0, cA1);                                             \
    float nvb = fmaxf(cB0, cB1);                                             \
    bool  IA  = cA1 > cA0;                                                   \
    bool  IB  = cB1 > cB0;                                                   \
    va = nva;  vb = nvb;                                                     \
    s  = warp_sum_r84(nva + nvb);                                            \
    ll = lln;  wt = wn;

// ---------------------------------------------------------------------------
// Forward ACS, windowed: one 32-thread block per (batch, chunk).
// Lane l holds states l (va) and l+32 (vb); predecessors of state l live in
// lane l>>1, of state l+32 in lane (l>>1)+16.
// ---------------------------------------------------------------------------
__global__ void __launch_bounds__(32, 1)
wcva_fwd(const float* __restrict__ x, const float* __restrict__ w,
         float* __restrict__ soft)
{
    const int b  = blockIdx.x >> 3;          // batch
    const int ck = blockIdx.x & 7;           // chunk

    const int body1 = 1280 + 256 * ck;
    const int body0 = (ck == 0) ? 1023 : body1 - 256;
    const int t0    = body0 - W_UP;

    const int l = threadIdx.x;
    const int h = l >> 1;

    const float2* __restrict__ xrow = (const float2*)(x + (size_t)b * (DET * 2));
    float* __restrict__ softrow = soft + (size_t)b * SOFT_ROW;
    uint8_t* __restrict__ surrow = g_sur + (size_t)b * 2048 * 32 + l;

    float sA0, sA1, sB0, sB1;
    int   dA0, dA1, dB0, dB1;
    edge_code(l,      h,      sA0, dA0);
    edge_code(l,      h + 32, sA1, dA1);
    edge_code(l + 32, h + 16, sB0, dB0);
    edge_code(l + 32, h + 48, sB1, dB1);

    // Uniform cold start (any uniform value is equivalent after per-step
    // mean subtraction once survivors merge inside the W_UP warm-up).
    float va = 0.0f;
    float vb = 0.0f;
    float s  = 0.0f;

    float2 ll = xrow[t0 & (DET - 1)];
    float  wt = __ldg(w + t0);

    // ---- warm-up: t in [t0, body0)  (no outputs) ----
#pragma unroll 2
    for (int t = t0; t < body0; t++) {
        float2 lln = xrow[(t + 1) & (DET - 1)];
        float  wn  = __ldg(w + t + 1);
        ACS_STEP(ia_, ib_)
        (void)ia_; (void)ib_;
    }

    if (ck < 4) {
        // Bodies of chunks 0-3 lie wholly in [1023, 2047]: soft + survivors.
        // Chunk 0's first body step t=1023 has soft output but no survivor.
        if (ck == 0) {
            float2 lln = xrow[1024 & (DET - 1)];
            float  wn  = __ldg(w + 1024);
            ACS_STEP(ia_, ib_)
            (void)ia_; (void)ib_;
            softrow[l]      = clipf(fmaf(-0.015625f, s, va));
            softrow[l + 32] = clipf(fmaf(-0.015625f, s, vb));
        }
        const int tb0 = (ck == 0) ? 1024 : body0;
#pragma unroll 2
        for (int t = tb0; t < body1; t++) {
            float2 lln = xrow[(t + 1) & (DET - 1)];
            float  wn  = __ldg(w + t + 1);
            ACS_STEP(ia, ib)
            surrow[(size_t)(t - 1024) * 32] =
                (uint8_t)((ia ? 1 : 0) | (ib ? 2 : 0));
            int r = (t - 1023) * 64;
            softrow[r + l]      = clipf(fmaf(-0.015625f, s, va));
            softrow[r + l + 32] = clipf(fmaf(-0.015625f, s, vb));
        }
    } else {
        // Bodies of chunks 4-7 lie wholly past the soft window: survivors only.
#pragma unroll 2
        for (int t = body0; t < body1; t++) {
            int tn = (t + 1 < T_TOT) ? t + 1 : t;
            float2 lln = xrow[tn & (DET - 1)];
            float  wn  = __ldg(w + tn);
            ACS_STEP(ia, ib)
            surrow[(size_t)(t - 1024) * 32] =
                (uint8_t)((ia ? 1 : 0) | (ib ? 2 : 0));
        }
    }
}

// ---------------------------------------------------------------------------
// Traceback phase A: per (batch, chunk) build the 64-entry state map over
// 32 survivor steps. Chunk c covers s = 2047-32c .. 2016-32c (descending).
// ---------------------------------------------------------------------------
__global__ void __launch_bounds__(64)
tb_maps()
{
    __shared__ uint8_t rows[1024];     // 32 steps x 32 lanes

    const int b = blockIdx.x >> 6;
    const int c = blockIdx.x & 63;
    const int s0 = 2047 - 32 * c;      // top (first-processed) row

    const uint4* __restrict__ src =
        (const uint4*)(g_sur + (((size_t)b * 2048) + (s0 - 31)) * 32);
    ((uint4*)rows)[threadIdx.x] = src[threadIdx.x];   // 64 x 16B = 1 KB
    __syncthreads();

    int st = threadIdx.x;              // entry state
#pragma unroll
    for (int k = 0; k < 32; k++) {
        uint8_t byt = rows[(31 - k) * 32 + (st & 31)];   // row s0-k
        int ind = (byt >> (st >> 5)) & 1;
        st = (st >> 1) + (ind << 5);
    }
    g_map[((size_t)b << 12) + (c << 6) + threadIdx.x] = (uint8_t)st;
}

// ---------------------------------------------------------------------------
// Traceback phase B+C: per batch, compose chunk maps serially from state 0
// at t = T-1, then re-trace the 32 output chunks (s < 1024) and emit bits.
// ---------------------------------------------------------------------------
__global__ void __launch_bounds__(256)
tb_emit(float* __restrict__ dec)
{
    __shared__ uint8_t smap[4096];     // 64 chunks x 64 entries
    __shared__ uint8_t ssur[32768];    // survivor bytes for s in [0, 1024)
    __shared__ uint8_t sentry[64];

    const int b   = blockIdx.x;
    const int tid = threadIdx.x;

    ((uint4*)smap)[tid] = ((const uint4*)(g_map + ((size_t)b << 12)))[tid];

    const uint4* __restrict__ ss = (const uint4*)(g_sur + (size_t)b * 2048 * 32);
#pragma unroll
    for (int i = 0; i < 8; i++)
        ((uint4*)ssur)[tid + 256 * i] = ss[tid + 256 * i];
    __syncthreads();

    if (tid == 0) {
        int st = 0;
        for (int c = 0; c < 64; c++) {
            sentry[c] = (uint8_t)st;
            st = smap[(c << 6) + st];
        }
    }
    __syncthreads();

    if (tid < 32) {
        int c  = 32 + tid;             // output chunks: s0 = 1023-32*tid
        int st = sentry[c];
        float* __restrict__ drow = dec + (size_t)b * DET;
        int s0 = 2047 - 32 * c;
#pragma unroll
        for (int k = 0; k < 32; k++) {
            int s = s0 - k;
            drow[s] = (float)(1 - (st & 1));     // bit from state BEFORE update
            uint8_t byt = ssur[s * 32 + (st & 31)];
            int ind = (byt >> (st >> 5)) & 1;
            st = (st >> 1) + (ind << 5);
        }
    }
}

// ---------------------------------------------------------------------------
// Harness entry. Output layout: decoded_words (256*1024 f32) then soft
// (256*65600 f32), concatenated.
// ---------------------------------------------------------------------------
extern "C" void kernel_launch(void* const* d_in, const int* in_sizes, int n_in,
                              void* d_out, int out_size)
{
    const float* x  = (const float*)d_in[0];   // (256, 2048)
    const float* wv = (const float*)d_in[1];   // (3072,)
    float* out  = (float*)d_out;

    float* dec  = out;                          // 256*1024
    float* soft = out + (size_t)BATCH * DET;    // 256*65600

    wcva_fwd<<<BATCH * NCH, 32>>>(x, wv, soft);
    tb_maps<<<BATCH * 64, 64>>>();
    tb_emit<<<BATCH, 256>>>(dec);
}

// round 12
// speedup vs baseline: 3.0927x; 1.0412x over previous
#include <cuda_runtime.h>
#include <stdint.h>

// Problem constants (fixed shapes from reference)
#define DET      1024
#define T_TOT    3072                 // DET * 3 replications
#define BATCH    256
#define CLAMP_V  50.0f
#define SOFT_ROW (1025 * 64)          // soft window rows * 64 states

// Windowed Viterbi: 8 chunks per batch, every chunk cold-started from a
// uniform metric W_UP steps before its body (survivor merge makes the body
// match the true run; uniform offsets cancel exactly in mean-subtraction).
//   chunk 0: body [1023, 1280)   chunks k>0: body [1280+256(k-1), +256)
// Bodies cover [1023, 3072) exactly. Chunks 0-3 lie in the soft window
// [1023, 2047]; chunks 4-7 produce survivor bytes only.
#define NCH      8
#define W_UP     704

// Survivor decisions: one byte per (batch, step t-1024, lane).
// bit0 = decision of state l (<32), bit1 = decision of state l+32.  16 MB.
__device__ uint8_t g_sur[(size_t)BATCH * 2048 * 32];
// Per-chunk traceback maps: [batch][chunk(64)][entry(64)] -> exit state. 1 MB.
__device__ uint8_t g_map[(size_t)BATCH * 64 * 64];

// Edge code: for new state n with predecessor p, coded bits are
//   c0 = (n&1) ^ p1 ^ p2 ^ p4 ^ p5 ;  c1 = (n&1) ^ p0 ^ p1 ^ p2 ^ p5
// bm = (1-2c0)*llr0 + (1-2c1)*llr1 = sgn * ((c0^c1) ? (llr0-llr1) : (llr0+llr1))
__device__ __forceinline__ void edge_code(int n, int p, float& sgn, int& dif)
{
    int c0 = ((n & 1) ^ (p >> 1) ^ (p >> 2) ^ (p >> 4) ^ (p >> 5)) & 1;
    int c1 = ((n & 1) ^  p       ^ (p >> 1) ^ (p >> 2) ^ (p >> 5)) & 1;
    sgn = c0 ? -1.0f : 1.0f;
    dif = (c0 ^ c1) & 1;
}

__device__ __forceinline__ float clipf(float v)
{
    return fminf(fmaxf(v, -CLAMP_V), CLAMP_V);
}

// Warp sum broadcast: radix-2 xor butterfly — minimal SHFL/instruction count
// (5 SHFL + 5 FADD). The kernel is now SHFL-throughput bound (L1 pipe 64.5%
// at R11), not chain bound, so fewer transactions beats shorter chain.
// Xor-symmetric -> bit-identical sum on every lane (uniform mean).
__device__ __forceinline__ float warp_sum_bfly(float s)
{
    s += __shfl_xor_sync(0xffffffffu, s, 1);
    s += __shfl_xor_sync(0xffffffffu, s, 2);
    s += __shfl_xor_sync(0xffffffffu, s, 4);
    s += __shfl_xor_sync(0xffffffffu, s, 8);
    s += __shfl_xor_sync(0xffffffffu, s, 16);
    return s;
}

// One full ACS step (same arithmetic class as the R6/R9/R11 passing kernels:
// the warp-sum grouping differs, but the mean stays uniform across lanes, so
// decisions and outputs are invariant to sub-ulp).
// Carried: va/vb = UNNORMALIZED max-results of the previous step, s = their
// warp sum. Destination applies zero-lag normalization p = clip(fma(-1/64,s,g)).
#define ACS_STEP(IA, IB)                                                     \
    float wS  = wt * (ll.x + ll.y);                                          \
    float wD  = wt * (ll.x - ll.y);                                          \
    float wA0 = dA0 ? wD : wS;                                               \
    float wA1 = dA1 ? wD : wS;                                               \
    float wB0 = dB0 ? wD : wS;                                               \
    float wB1 = dB1 ? wD : wS;                                               \
    float gA0 = __shfl_sync(0xffffffffu, va, h);                             \
    float gA1 = __shfl_sync(0xffffffffu, vb, h);                             \
    float gB0 = __shfl_sync(0xffffffffu, va, h + 16);                        \
    float gB1 = __shfl_sync(0xffffffffu, vb, h + 16);                        \
    float pA0 = clipf(fmaf(-0.015625f, s, gA0));                             \
    float pA1 = clipf(fmaf(-0.015625f, s, gA1));                             \
    float pB0 = clipf(fmaf(-0.015625f, s, gB0));                             \
    float pB1 = clipf(fmaf(-0.015625f, s, gB1));                             \
    float cA0 = fmaf(sA0, wA0, pA0);                                         \
    float cA1 = fmaf(sA1, wA1, pA1);                                         \
    float cB0 = fmaf(sB0, wB0, pB0);                                         \
    float cB1 = fmaf(sB1, wB1, pB1);                                         \
    float nva = fmaxf(cA0, cA1);                                             \
    float nvb = fmaxf(cB0, cB1);                                             \
    bool  IA  = cA1 > cA0;                                                   \
    bool  IB  = cB1 > cB0;                                                   \
    va = nva;  vb = nvb;                                                     \
    s  = warp_sum_bfly(nva + nvb);                                           \
    ll = lln;  wt = wn;

// ---------------------------------------------------------------------------
// Forward ACS, windowed: one 32-thread block per (batch, chunk).
// Lane l holds states l (va) and l+32 (vb); predecessors of state l live in
// lane l>>1, of state l+32 in lane (l>>1)+16.
// ---------------------------------------------------------------------------
__global__ void __launch_bounds__(32, 1)
wcva_fwd(const float* __restrict__ x, const float* __restrict__ w,
         float* __restrict__ soft)
{
    const int b  = blockIdx.x >> 3;          // batch
    const int ck = blockIdx.x & 7;           // chunk

    const int body1 = 1280 + 256 * ck;
    const int body0 = (ck == 0) ? 1023 : body1 - 256;
    const int t0    = body0 - W_UP;

    const int l = threadIdx.x;
    const int h = l >> 1;

    const float2* __restrict__ xrow = (const float2*)(x + (size_t)b * (DET * 2));
    float* __restrict__ softrow = soft + (size_t)b * SOFT_ROW;
    uint8_t* __restrict__ surrow = g_sur + (size_t)b * 2048 * 32 + l;

    float sA0, sA1, sB0, sB1;
    int   dA0, dA1, dB0, dB1;
    edge_code(l,      h,      sA0, dA0);
    edge_code(l,      h + 32, sA1, dA1);
    edge_code(l + 32, h + 16, sB0, dB0);
    edge_code(l + 32, h + 48, sB1, dB1);

    // Uniform cold start (any uniform value is equivalent after per-step
    // mean subtraction once survivors merge inside the W_UP warm-up).
    float va = 0.0f;
    float vb = 0.0f;
    float s  = 0.0f;

    float2 ll = xrow[t0 & (DET - 1)];
    float  wt = __ldg(w + t0);

    // ---- warm-up: t in [t0, body0)  (no outputs) ----
#pragma unroll 2
    for (int t = t0; t < body0; t++) {
        float2 lln = xrow[(t + 1) & (DET - 1)];
        float  wn  = __ldg(w + t + 1);
        ACS_STEP(ia_, ib_)
        (void)ia_; (void)ib_;
    }

    if (ck < 4) {
        // Bodies of chunks 0-3 lie wholly in [1023, 2047]: soft + survivors.
        // Chunk 0's first body step t=1023 has soft output but no survivor.
        if (ck == 0) {
            float2 lln = xrow[1024 & (DET - 1)];
            float  wn  = __ldg(w + 1024);
            ACS_STEP(ia_, ib_)
            (void)ia_; (void)ib_;
            softrow[l]      = clipf(fmaf(-0.015625f, s, va));
            softrow[l + 32] = clipf(fmaf(-0.015625f, s, vb));
        }
        const int tb0 = (ck == 0) ? 1024 : body0;
#pragma unroll 2
        for (int t = tb0; t < body1; t++) {
            float2 lln = xrow[(t + 1) & (DET - 1)];
            float  wn  = __ldg(w + t + 1);
            ACS_STEP(ia, ib)
            surrow[(size_t)(t - 1024) * 32] =
                (uint8_t)((ia ? 1 : 0) | (ib ? 2 : 0));
            int r = (t - 1023) * 64;
            softrow[r + l]      = clipf(fmaf(-0.015625f, s, va));
            softrow[r + l + 32] = clipf(fmaf(-0.015625f, s, vb));
        }
    } else {
        // Bodies of chunks 4-7 lie wholly past the soft window: survivors only.
#pragma unroll 2
        for (int t = body0; t < body1; t++) {
            int tn = (t + 1 < T_TOT) ? t + 1 : t;
            float2 lln = xrow[tn & (DET - 1)];
            float  wn  = __ldg(w + tn);
            ACS_STEP(ia, ib)
            surrow[(size_t)(t - 1024) * 32] =
                (uint8_t)((ia ? 1 : 0) | (ib ? 2 : 0));
        }
    }
}

// ---------------------------------------------------------------------------
// Traceback phase A: per (batch, chunk) build the 64-entry state map over
// 32 survivor steps. Chunk c covers s = 2047-32c .. 2016-32c (descending).
// ---------------------------------------------------------------------------
__global__ void __launch_bounds__(64)
tb_maps()
{
    __shared__ uint8_t rows[1024];     // 32 steps x 32 lanes

    const int b = blockIdx.x >> 6;
    const int c = blockIdx.x & 63;
    const int s0 = 2047 - 32 * c;      // top (first-processed) row

    const uint4* __restrict__ src =
        (const uint4*)(g_sur + (((size_t)b * 2048) + (s0 - 31)) * 32);
    ((uint4*)rows)[threadIdx.x] = src[threadIdx.x];   // 64 x 16B = 1 KB
    __syncthreads();

    int st = threadIdx.x;              // entry state
#pragma unroll
    for (int k = 0; k < 32; k++) {
        uint8_t byt = rows[(31 - k) * 32 + (st & 31)];   // row s0-k
        int ind = (byt >> (st >> 5)) & 1;
        st = (st >> 1) + (ind << 5);
    }
    g_map[((size_t)b << 12) + (c << 6) + threadIdx.x] = (uint8_t)st;
}

// ---------------------------------------------------------------------------
// Traceback phase B+C: per batch, compose chunk maps serially from state 0
// at t = T-1, then re-trace the 32 output chunks (s < 1024) and emit bits.
// ---------------------------------------------------------------------------
__global__ void __launch_bounds__(256)
tb_emit(float* __restrict__ dec)
{
    __shared__ uint8_t smap[4096];     // 64 chunks x 64 entries
    __shared__ uint8_t ssur[32768];    // survivor bytes for s in [0, 1024)
    __shared__ uint8_t sentry[64];

    const int b   = blockIdx.x;
    const int tid = threadIdx.x;

    ((uint4*)smap)[tid] = ((const uint4*)(g_map + ((size_t)b << 12)))[tid];

    const uint4* __restrict__ ss = (const uint4*)(g_sur + (size_t)b * 2048 * 32);
#pragma unroll
    for (int i = 0; i < 8; i++)
        ((uint4*)ssur)[tid + 256 * i] = ss[tid + 256 * i];
    __syncthreads();

    if (tid == 0) {
        int st = 0;
        for (int c = 0; c < 64; c++) {
            sentry[c] = (uint8_t)st;
            st = smap[(c << 6) + st];
        }
    }
    __syncthreads();

    if (tid < 32) {
        int c  = 32 + tid;             // output chunks: s0 = 1023-32*tid
        int st = sentry[c];
        float* __restrict__ drow = dec + (size_t)b * DET;
        int s0 = 2047 - 32 * c;
#pragma unroll
        for (int k = 0; k < 32; k++) {
            int s = s0 - k;
            drow[s] = (float)(1 - (st & 1));     // bit from state BEFORE update
            uint8_t byt = ssur[s * 32 + (st & 31)];
            int ind = (byt >> (st >> 5)) & 1;
            st = (st >> 1) + (ind << 5);
        }
    }
}

// ---------------------------------------------------------------------------
// Harness entry. Output layout: decoded_words (256*1024 f32) then soft
// (256*65600 f32), concatenated.
// ---------------------------------------------------------------------------
extern "C" void kernel_launch(void* const* d_in, const int* in_sizes, int n_in,
                              void* d_out, int out_size)
{
    const float* x  = (const float*)d_in[0];   // (256, 2048)
    const float* wv = (const float*)d_in[1];   // (3072,)
    float* out  = (float*)d_out;

    float* dec  = out;                          // 256*1024
    float* soft = out + (size_t)BATCH * DET;    // 256*65600

    wcva_fwd<<<BATCH * NCH, 32>>>(x, wv, soft);
    tb_maps<<<BATCH * 64, 64>>>();
    tb_emit<<<BATCH, 256>>>(dec);
}